// round 11
// baseline (speedup 1.0000x reference)
#include <cuda_runtime.h>
#include <cuda_fp16.h>
#include <math.h>
#include <stdint.h>

// Problem constants
#define B_    2
#define S_    4096
#define D_    2048
#define H_    16
#define HD_   128
#define C_    64
#define NC_   64
#define M_    (B_*S_)        // 8192 tokens
#define N1_   (5*D_)         // 10240
#define LANES_ (B_*H_*HD_)   // 4096
#define RMS_EPS 1.1920928955078125e-07f

// -------- scratch (static device globals; no runtime allocation) --------
__device__ float g_proj[M_*(size_t)N1_];   // [8192,10240] projection
__device__ float g_mem [M_*(size_t)D_];    // memory states [B*S, D]
__device__ float g_y   [M_*(size_t)D_];    // gated output  [B*S, D]
__device__ float g_Pc  [NC_*LANES_];       // per-chunk cumprod end
__device__ float g_Ac  [NC_*LANES_];       // per-chunk acc end
__device__ float g_S0  [NC_*LANES_];       // chunk-start states

__device__ __forceinline__ float sigmoidf_(float x) {
    return 1.0f / (1.0f + expf(-x));
}

// ===================== fp16 mma.sync GEMM =====================
// C[M,N] = A[M,K] @ B[N,K]^T, fp32 in/out, f16 m16n8k16 mma with fp32 accum.
// BM=128 x BN=128 x BK=32, 256 threads (8 warps 2x4), warp tile 64x32.
// cp.async fp32 -> staging (double buffered); cooperative convert to fp16
// tiles (rows padded to 40 halves = 80B, conflict-free ldmatrix); ldmatrix.x4
// fragment loads; 8x8 CTA supertile rasterization for L2 reuse.

#define BM 128
#define BN 128
#define BK 32
#define HPAD 40                             // halves per padded row (80B)
#define STAGE_F (BM*BK + BN*BK)             // 8192 floats per stage
#define SM_STAGE_BYTES (2*STAGE_F*4)        // 65536
#define SM_HA_OFF SM_STAGE_BYTES            // 65536
#define SM_HA_BYTES (BM*HPAD*2)             // 10240
#define SM_HB_OFF (SM_HA_OFF + SM_HA_BYTES) // 75776
#define SM_HB_BYTES (BN*HPAD*2)             // 10240
#define SMEM_BYTES (SM_HB_OFF + SM_HB_BYTES) // 86016

#define CP_ASYNC16(dst, src) \
    asm volatile("cp.async.cg.shared.global [%0], [%1], 16;" \
                 :: "r"(dst), "l"(src) : "memory")
#define CP_COMMIT() asm volatile("cp.async.commit_group;" ::: "memory")
#define CP_WAIT0()  asm volatile("cp.async.wait_group 0;" ::: "memory")

#define LDMATRIX_X4(r, addr) \
    asm volatile("ldmatrix.sync.aligned.m8n8.x4.shared.b16 {%0,%1,%2,%3}, [%4];" \
                 : "=r"((r)[0]), "=r"((r)[1]), "=r"((r)[2]), "=r"((r)[3]) \
                 : "r"(addr))

static __device__ __forceinline__ void mma_f16(float* c, const uint32_t* a,
                                               const uint32_t* b) {
    asm volatile(
        "mma.sync.aligned.m16n8k16.row.col.f32.f16.f16.f32 "
        "{%0,%1,%2,%3}, {%4,%5,%6,%7}, {%8,%9}, {%0,%1,%2,%3};"
        : "+f"(c[0]), "+f"(c[1]), "+f"(c[2]), "+f"(c[3])
        : "r"(a[0]), "r"(a[1]), "r"(a[2]), "r"(a[3]), "r"(b[0]), "r"(b[1]));
}

__global__ void __launch_bounds__(256, 2)
gemm_f16(const float* __restrict__ A, const float* __restrict__ Bmat,
         float* __restrict__ C, int M, int N, int K) {
    extern __shared__ char smc[];
    float* stage = reinterpret_cast<float*>(smc);
    const uint32_t sHA = (uint32_t)__cvta_generic_to_shared(smc + SM_HA_OFF);
    const uint32_t sHB = (uint32_t)__cvta_generic_to_shared(smc + SM_HB_OFF);

    const int tid = threadIdx.x;
    const int wid = tid >> 5;
    const int lane = tid & 31;
    const int g = lane >> 2;
    const int t = lane & 3;
    const int warp_m = wid >> 2;      // 0..1
    const int warp_n = wid & 3;       // 0..3

    // 8x8 supertile rasterization over (N/128) x (M/128) CTA grid
    const int gxc = N >> 10;                      // (N/128)/8
    const int group = blockIdx.x >> 6;
    const int within = blockIdx.x & 63;
    const int bx = (group % gxc) * 8 + (within & 7);
    const int by = (group / gxc) * 8 + (within >> 3);

    const long Arow0 = (long)by * BM;
    const long Brow0 = (long)bx * BN;
    const int ntiles = K / BK;

    float acc[4][4][4];
#pragma unroll
    for (int mt = 0; mt < 4; mt++)
#pragma unroll
        for (int nt = 0; nt < 4; nt++)
#pragma unroll
            for (int r = 0; r < 4; r++) acc[mt][nt][r] = 0.0f;

    // cp.async one stage of raw fp32 (A tile 128x32, B tile 128x32)
    auto load_stage = [&](int s, int kt) {
        float* st = stage + s * STAGE_F;
        const float* Asrc = A + Arow0 * K + (long)kt * BK;
        const float* Bsrc = Bmat + Brow0 * K + (long)kt * BK;
#pragma unroll
        for (int q = 0; q < 8; q++) {               // 2048 16B chunks / 256 thr
            int ci = q * 256 + tid;
            int row = (ci & 1023) >> 3;
            int inner = ci & 7;
            if (ci < 1024) {
                uint32_t d = (uint32_t)__cvta_generic_to_shared(
                    st + row * BK + inner * 4);
                CP_ASYNC16(d, Asrc + (long)row * K + inner * 4);
            } else {
                uint32_t d = (uint32_t)__cvta_generic_to_shared(
                    st + BM * BK + row * BK + inner * 4);
                CP_ASYNC16(d, Bsrc + (long)row * K + inner * 4);
            }
        }
        CP_COMMIT();
    };

    // per-thread ldmatrix address offsets (bytes)
    const int a_lm = ((lane & 7) + ((lane >> 3) & 1) * 8) * (HPAD * 2)
                   + ((lane >> 4) & 1) * 16;
    const int b_lm = ((lane & 7) + ((lane >> 4) & 1) * 8) * (HPAD * 2)
                   + ((lane >> 3) & 1) * 16;

    load_stage(0, 0);

    for (int kt = 0; kt < ntiles; kt++) {
        const int cur = kt & 1;
        CP_WAIT0();
        __syncthreads();

        // cooperative fp32 -> fp16 convert: thread i handles row i
        {
            const float* srow = stage + cur * STAGE_F + tid * BK;
            __half* hrow = (tid < BM)
                ? reinterpret_cast<__half*>(smc + SM_HA_OFF) + tid * HPAD
                : reinterpret_cast<__half*>(smc + SM_HB_OFF) + (tid - BM) * HPAD;
            uint32_t h[16];
#pragma unroll
            for (int jj = 0; jj < 8; jj++) {
                int j = (tid + jj) & 7;
                float4 v = reinterpret_cast<const float4*>(srow)[j];
                __half2 p0 = __floats2half2_rn(v.x, v.y);
                __half2 p1 = __floats2half2_rn(v.z, v.w);
                h[2 * j]     = *reinterpret_cast<uint32_t*>(&p0);
                h[2 * j + 1] = *reinterpret_cast<uint32_t*>(&p1);
            }
#pragma unroll
            for (int m = 0; m < 4; m++)
                reinterpret_cast<uint4*>(hrow)[m] =
                    make_uint4(h[4 * m], h[4 * m + 1], h[4 * m + 2], h[4 * m + 3]);
        }
        __syncthreads();

        if (kt + 1 < ntiles) load_stage(cur ^ 1, kt + 1);

        // compute: two k16 steps
#pragma unroll
        for (int s = 0; s < 2; s++) {
            uint32_t af[4][4], bf[2][4];
#pragma unroll
            for (int mt = 0; mt < 4; mt++)
                LDMATRIX_X4(af[mt],
                    sHA + (warp_m * 64 + mt * 16) * (HPAD * 2) + s * 32 + a_lm);
#pragma unroll
            for (int pr = 0; pr < 2; pr++)
                LDMATRIX_X4(bf[pr],
                    sHB + (warp_n * 32 + pr * 16) * (HPAD * 2) + s * 32 + b_lm);
#pragma unroll
            for (int mt = 0; mt < 4; mt++)
#pragma unroll
                for (int nt = 0; nt < 4; nt++)
                    mma_f16(acc[mt][nt], af[mt], &bf[nt >> 1][(nt & 1) * 2]);
        }
        __syncthreads();
    }

    // epilogue: c0/c1 at (g, 2t), c2/c3 at (g+8, 2t)
#pragma unroll
    for (int mt = 0; mt < 4; mt++) {
#pragma unroll
        for (int nt = 0; nt < 4; nt++) {
            long row = Arow0 + warp_m * 64 + mt * 16 + g;
            long col = Brow0 + warp_n * 32 + nt * 8 + 2 * t;
            *reinterpret_cast<float2*>(C + row * N + col) =
                make_float2(acc[mt][nt][0], acc[mt][nt][1]);
            *reinterpret_cast<float2*>(C + (row + 8) * N + col) =
                make_float2(acc[mt][nt][2], acc[mt][nt][3]);
        }
    }
}

// ===================== Phase 1: per-chunk (cumprod end, acc end) =====================
__global__ void chunk_summary_kernel() {
    int idx = blockIdx.x * blockDim.x + threadIdx.x;
    if (idx >= NC_ * LANES_) return;
    int c = idx >> 12;
    int lane = idx & 4095;
    int b = lane >> 11;
    int rem = lane & 2047;

    const float* base = g_proj + (long)(b * S_ + c * C_) * N1_ + rem;
    float prefix = 1.0f, acc = 0.0f;
#pragma unroll 4
    for (int t = 0; t < C_; t++) {
        const float* r = base + (long)t * N1_;
        float kr = r[D_];
        float vr = r[2 * D_];
        float ar = r[3 * D_];
        float a = fminf(fmaxf(sigmoidf_(ar + 2.0f), 0.6f), 0.9995f);
        float u = tanhf(kr) * vr;
        prefix *= a;
        acc += u / fmaxf(prefix, 1e-6f);
    }
    g_Pc[idx] = prefix;
    g_Ac[idx] = acc;
}

// ===================== Phase 2: sequential chunk-level scan =====================
__global__ void chunk_state_kernel() {
    int lane = blockIdx.x * blockDim.x + threadIdx.x;
    if (lane >= LANES_) return;
    float state = 0.0f;
#pragma unroll
    for (int c = 0; c < NC_; c++) {
        int idx = c * LANES_ + lane;
        g_S0[idx] = state;
        state = g_Pc[idx] * (state + g_Ac[idx]);
    }
}

// ===================== Phase 3: per-element memory states =====================
__global__ void mem_kernel() {
    int idx = blockIdx.x * blockDim.x + threadIdx.x;
    if (idx >= NC_ * LANES_) return;
    int c = idx >> 12;
    int lane = idx & 4095;
    int b = lane >> 11;
    int rem = lane & 2047;

    const float* base = g_proj + (long)(b * S_ + c * C_) * N1_ + rem;
    float* mout = g_mem + (long)(b * S_ + c * C_) * D_ + rem;
    float state = g_S0[idx];
    float prefix = 1.0f, acc = 0.0f;
#pragma unroll 4
    for (int t = 0; t < C_; t++) {
        const float* r = base + (long)t * N1_;
        float kr = r[D_];
        float vr = r[2 * D_];
        float ar = r[3 * D_];
        float a = fminf(fmaxf(sigmoidf_(ar + 2.0f), 0.6f), 0.9995f);
        float u = tanhf(kr) * vr;
        prefix *= a;
        acc += u / fmaxf(prefix, 1e-6f);
        mout[(long)t * D_] = prefix * (state + acc);
    }
}

// ========== Phase 4: RMS-norm(q), gating, y = gate*(q*mem) + (1-gate)*v ==========
__global__ void finalize_kernel() {
    int w = (blockIdx.x * blockDim.x + threadIdx.x) >> 5;
    int lanei = threadIdx.x & 31;
    if (w >= M_ * H_) return;
    int m = w >> 4;
    int h = w & 15;
    int d = h * HD_ + lanei * 4;

    const float* row = g_proj + (long)m * N1_;
    float4 q4 = *reinterpret_cast<const float4*>(row + d);
    float ss = q4.x * q4.x + q4.y * q4.y + q4.z * q4.z + q4.w * q4.w;
#pragma unroll
    for (int off = 16; off; off >>= 1)
        ss += __shfl_xor_sync(0xffffffffu, ss, off);
    float scale = rsqrtf(ss * (1.0f / 128.0f) + RMS_EPS);

    float4 v4 = *reinterpret_cast<const float4*>(row + 2 * D_ + d);
    float4 g4 = *reinterpret_cast<const float4*>(row + 4 * D_ + d);
    float4 mm = *reinterpret_cast<const float4*>(g_mem + (long)m * D_ + d);

    float4 y;
    {
        float gt = sigmoidf_(g4.x);
        y.x = gt * (q4.x * scale * mm.x) + (1.0f - gt) * v4.x;
        gt = sigmoidf_(g4.y);
        y.y = gt * (q4.y * scale * mm.y) + (1.0f - gt) * v4.y;
        gt = sigmoidf_(g4.z);
        y.z = gt * (q4.z * scale * mm.z) + (1.0f - gt) * v4.z;
        gt = sigmoidf_(g4.w);
        y.w = gt * (q4.w * scale * mm.w) + (1.0f - gt) * v4.w;
    }
    *reinterpret_cast<float4*>(g_y + (long)m * D_ + d) = y;
}

// ================================ launcher ================================
extern "C" void kernel_launch(void* const* d_in, const int* in_sizes, int n_in,
                              void* d_out, int out_size) {
    const float* x     = (const float*)d_in[0];   // [2,4096,2048]
    const float* w_in  = (const float*)d_in[1];   // [10240,2048]
    const float* w_out = (const float*)d_in[2];   // [2048,2048]
    float* out = (float*)d_out;                   // [2,4096,2048]

    float *proj_p, *y_p;
    cudaGetSymbolAddress((void**)&proj_p, g_proj);
    cudaGetSymbolAddress((void**)&y_p, g_y);

    cudaFuncSetAttribute(gemm_f16, cudaFuncAttributeMaxDynamicSharedMemorySize,
                         SMEM_BYTES);

    // GEMM1: proj = x @ w_in^T   (f16 mma, fp32 accum)
    gemm_f16<<<(N1_ / BN) * (M_ / BM), 256, SMEM_BYTES>>>(x, w_in, proj_p,
                                                          M_, N1_, D_);
    // Scan pipeline
    chunk_summary_kernel<<<(NC_ * LANES_) / 256, 256>>>();
    chunk_state_kernel<<<LANES_ / 256, 256>>>();
    mem_kernel<<<(NC_ * LANES_) / 256, 256>>>();
    finalize_kernel<<<(M_ * H_ * 32) / 256, 256>>>();
    // GEMM2: out = y @ w_out^T
    gemm_f16<<<(D_ / BN) * (M_ / BM), 256, SMEM_BYTES>>>(y_p, w_out, out,
                                                         M_, D_, D_);
}